// round 16
// baseline (speedup 1.0000x reference)
#include <cuda_runtime.h>
#include <cuda_fp16.h>
#include <cstdint>
#include <math.h>

#define T_TOK 4096
#define DM    1024
#define NE    16
#define CAP   1024
#define DFF   512
#define DFS   1024
#define NTHR  512

// ---------------- scratch ----------------
__device__ int   g_cnt[NE];
__device__ int   g_slot[T_TOK * 2];
__device__ float g_wt[T_TOK * 2];
__device__ float g_Y [(size_t)NE * CAP * DM];

// activations: fp16
__device__ __half g_Xf [(size_t)NE * CAP * DM];
__device__ __half g_Hf [(size_t)NE * CAP * DFF];
__device__ __half g_hsf[(size_t)T_TOK * DM];
__device__ __half g_Hsf[(size_t)T_TOK * DFS];

// weights: fp16, transposed to [N, K]
__device__ __half g_w1f[(size_t)NE * DFF * DM];
__device__ __half g_w3f[(size_t)NE * DFF * DM];
__device__ __half g_w2f[(size_t)NE * DM * DFF];
__device__ __half g_ws1f[(size_t)DFS * DM];
__device__ __half g_ws3f[(size_t)DFS * DM];
__device__ __half g_ws2f[(size_t)DM * DFS];

// ---------------- helpers ----------------
__device__ __forceinline__ uint32_t smem_u32(const void* p) {
    uint32_t r;
    asm("{ .reg .u64 t; cvta.to.shared.u64 t, %1; cvt.u32.u64 %0, t; }" : "=r"(r) : "l"(p));
    return r;
}

#define LDSM_X4(r0, r1, r2, r3, addr) \
    asm volatile("ldmatrix.sync.aligned.m8n8.x4.shared.b16 {%0,%1,%2,%3}, [%4];" \
                 : "=r"(r0), "=r"(r1), "=r"(r2), "=r"(r3) : "r"(addr))

__device__ __forceinline__ void mma_f16(float* c, const uint32_t* a, const uint32_t* b) {
    asm volatile("mma.sync.aligned.m16n8k16.row.col.f32.f16.f16.f32 "
                 "{%0,%1,%2,%3}, {%4,%5,%6,%7}, {%8,%9}, {%0,%1,%2,%3};"
                 : "+f"(c[0]), "+f"(c[1]), "+f"(c[2]), "+f"(c[3])
                 : "r"(a[0]), "r"(a[1]), "r"(a[2]), "r"(a[3]), "r"(b[0]), "r"(b[1]));
}

#define CP_ASYNC16(dst, src) \
    asm volatile("{ .reg .u64 g; cvta.to.global.u64 g, %1; " \
                 "cp.async.cg.shared.global [%0], [g], 16; }" \
                 :: "r"(dst), "l"(src) : "memory")
#define CP_COMMIT() asm volatile("cp.async.commit_group;" ::: "memory")
#define CP_WAIT(n)  asm volatile("cp.async.wait_group %0;" :: "n"(n) : "memory")

__device__ __forceinline__ uint32_t swz(uint32_t base, int r, int byteoff) {
    return base + (uint32_t)(r * 128) + (uint32_t)(((((byteoff >> 4) ^ (r & 7)) << 4)) | (byteoff & 15));
}

// A tile: 128 rows x 64 k (16KB)
__device__ __forceinline__ void cpa_tile(const __half* __restrict__ src, int ldk, uint32_t dst) {
    const int tid = threadIdx.x;
#pragma unroll
    for (int k = 0; k < 2; k++) {
        const int i = tid + k * NTHR;
        const int r = i >> 3, c = i & 7;
        const uint32_t off = (uint32_t)(r * 128 + ((c ^ (r & 7)) << 4));
        CP_ASYNC16(dst + off, src + (size_t)r * ldk + c * 8);
    }
}

// B tile: 256 rows x 64 k (32KB), single source
__device__ __forceinline__ void cpa_tile256(const __half* __restrict__ src, int ldk, uint32_t dst) {
    const int tid = threadIdx.x;
#pragma unroll
    for (int k = 0; k < 4; k++) {
        const int i = tid + k * NTHR;
        const int r = i >> 3, c = i & 7;
        const uint32_t off = (uint32_t)(r * 128 + ((c ^ (r & 7)) << 4));
        CP_ASYNC16(dst + off, src + (size_t)r * ldk + c * 8);
    }
}

// B tile: rows 0..127 from b1, 128..255 from b3 (SwiGLU)
__device__ __forceinline__ void cpa_tile_dual256(const __half* __restrict__ b1,
                                                 const __half* __restrict__ b3,
                                                 int ldk, uint32_t dst) {
    const int tid = threadIdx.x;
#pragma unroll
    for (int k = 0; k < 4; k++) {
        const int i = tid + k * NTHR;
        const int r = i >> 3, c = i & 7;
        const __half* s = (r < 128) ? b1 + (size_t)r * ldk + c * 8
                                    : b3 + (size_t)(r - 128) * ldk + c * 8;
        const uint32_t off = (uint32_t)(r * 128 + ((c ^ (r & 7)) << 4));
        CP_ASYNC16(dst + off, s);
    }
}

#define NSTAGE 4
#define STAGE_BYTES 49152           // A(16K) + B(32K)
#define SMEM_BYTES (NSTAGE * STAGE_BYTES + 1024)

// ---------------- weight transpose + fp16 convert prepass (float4 loads) ----------------
__device__ __forceinline__ void wsplit_tile(const float* __restrict__ W,
                                            __half* __restrict__ of,
                                            int K, int N, int e, int rem) {
    const int ntiles_n = N >> 5;
    const int kb = (rem / ntiles_n) * 32, nb = (rem % ntiles_n) * 32;
    const size_t eoff = (size_t)e * K * N;
    W += eoff; of += eoff;

    __shared__ float t[32][33];
    const int u = threadIdx.y * 32 + threadIdx.x;   // 0..255
    // vectorized load: one float4 per thread covers the 32x32 tile
    const int kr = u >> 3;                // k row 0..31
    const int cg = (u & 7) * 4;           // n col group 0,4,...,28
    float4 v = *reinterpret_cast<const float4*>(&W[(size_t)(kb + kr) * N + nb + cg]);
    t[kr][cg] = v.x; t[kr][cg + 1] = v.y; t[kr][cg + 2] = v.z; t[kr][cg + 3] = v.w;
    __syncthreads();

    const int nl = u >> 4;
    const int kp = u & 15;
#pragma unroll
    for (int i = 0; i < 2; i++) {
        const int n = nb + nl + 16 * i;
        __half2 h = __floats2half2_rn(t[2 * kp][nl + 16 * i], t[2 * kp + 1][nl + 16 * i]);
        *reinterpret_cast<__half2*>(of + (size_t)n * K + kb + 2 * kp) = h;
    }
}

__global__ void wsplit_up(const float* __restrict__ w1, const float* __restrict__ w3,
                          const float* __restrict__ ws1, const float* __restrict__ ws3) {
    int id = blockIdx.x;
    if (id < 8192)       { wsplit_tile(w1,  g_w1f,  DM, DFF, id >> 9, id & 511); }
    else if (id < 16384) { id -= 8192;  wsplit_tile(w3,  g_w3f,  DM, DFF, id >> 9, id & 511); }
    else if (id < 17408) { id -= 16384; wsplit_tile(ws1, g_ws1f, DM, DFS, 0, id); }
    else                 { id -= 17408; wsplit_tile(ws3, g_ws3f, DM, DFS, 0, id); }
}

__global__ void wsplit_down(const float* __restrict__ w2, const float* __restrict__ ws2) {
    int id = blockIdx.x;
    if (id < 8192) { wsplit_tile(w2, g_w2f, DFF, DM, id >> 9, id & 511); }
    else           { id -= 8192; wsplit_tile(ws2, g_ws2f, DFS, DM, 0, id); }
}

// ---------------- counters reset ----------------
__global__ void zero_cnt_kernel() {
    if (threadIdx.x < NE) g_cnt[threadIdx.x] = 0;
}

// ---------------- router ----------------
__global__ void router_kernel(const float* __restrict__ hs, const float* __restrict__ Wg) {
    __shared__ float sW[NE * 513];
    const int tid = threadIdx.x, lane = tid & 31, wid = tid >> 5;
    const int t = blockIdx.x * 8 + wid;

    float hreg[32];
#pragma unroll
    for (int j = 0; j < 32; j++) hreg[j] = hs[(size_t)t * DM + j * 32 + lane];

    __half hh[32];
#pragma unroll
    for (int j = 0; j < 32; j++) hh[j] = __float2half_rn(hreg[j]);
#pragma unroll
    for (int j = 0; j < 32; j++)
        g_hsf[(size_t)t * DM + j * 32 + lane] = hh[j];

    float plog[NE];
#pragma unroll
    for (int e = 0; e < NE; e++) plog[e] = 0.f;

    for (int c = 0; c < 2; c++) {
        __syncthreads();
        for (int i = tid; i < 512 * NE; i += 256) {
            int d = i >> 4, e = i & 15;
            sW[e * 513 + d] = Wg[(size_t)c * 8192 + i];
        }
        __syncthreads();
#pragma unroll
        for (int e = 0; e < NE; e++) {
            float s = 0.f;
#pragma unroll
            for (int j = 0; j < 16; j++)
                s += hreg[c * 16 + j] * sW[e * 513 + j * 32 + lane];
            plog[e] += s;
        }
    }
#pragma unroll
    for (int e = 0; e < NE; e++) {
        float v = plog[e];
#pragma unroll
        for (int o = 16; o > 0; o >>= 1) v += __shfl_xor_sync(0xffffffffu, v, o);
        plog[e] = v;
    }
    float mx = plog[0];
#pragma unroll
    for (int e = 1; e < NE; e++) mx = fmaxf(mx, plog[e]);
#pragma unroll
    for (int e = 0; e < NE; e++) plog[e] = expf(plog[e] - mx);
    int e0 = 0; float p0 = plog[0];
#pragma unroll
    for (int e = 1; e < NE; e++) if (plog[e] > p0) { p0 = plog[e]; e0 = e; }
    int e1 = 0; float p1 = -1.f;
#pragma unroll
    for (int e = 0; e < NE; e++) if (e != e0 && plog[e] > p1) { p1 = plog[e]; e1 = e; }
    const float rnorm = 1.f / (p0 + p1);
    const float w0 = p0 * rnorm, w1 = p1 * rnorm;

    int s0 = 0, s1 = 0;
    if (lane == 0) {
        int pos = atomicAdd(&g_cnt[e0], 1);
        s0 = (pos < CAP) ? e0 * CAP + pos : -1;
        pos = atomicAdd(&g_cnt[e1], 1);
        s1 = (pos < CAP) ? e1 * CAP + pos : -1;
        g_slot[t * 2] = s0; g_slot[t * 2 + 1] = s1;
        g_wt[t * 2] = w0;   g_wt[t * 2 + 1] = w1;
    }
    s0 = __shfl_sync(0xffffffffu, s0, 0);
    s1 = __shfl_sync(0xffffffffu, s1, 0);
    if (s0 >= 0) {
#pragma unroll
        for (int j = 0; j < 32; j++)
            g_Xf[(size_t)s0 * DM + j * 32 + lane] = hh[j];
    }
    if (s1 >= 0) {
#pragma unroll
        for (int j = 0; j < 32; j++)
            g_Xf[(size_t)s1 * DM + j * 32 + lane] = hh[j];
    }
}

// ======================= fp16 1-term HMMA GEMM kernels (R12 config) =======================
// 16 warps as 4(M) x 4(N); warp tile 32 rows x 64 cols; per warp per kk:
// 2 A-LDSM + 4 B-LDSM, 16 MMA.

__device__ __forceinline__ void ld_a16(uint32_t sA, int r0, int lane, int kk, uint32_t a[4]) {
    const int r = r0 + (lane & 15);
    const int byte = kk * 32 + ((lane >> 4) << 4);
    LDSM_X4(a[0], a[1], a[2], a[3], swz(sA, r, byte));
}

__device__ __forceinline__ void ld_b_pair(uint32_t sB, int nb, int lane, int kk, uint32_t b[4]) {
    const int r = nb + ((lane >> 4) << 3) + (lane & 7);
    const int byte = kk * 32 + (((lane >> 3) & 1) << 4);
    LDSM_X4(b[0], b[1], b[2], b[3], swz(sB, r, byte));
}

__device__ __forceinline__ float silu_f(float x) {
    return x / (1.f + __expf(-x));
}

// stage layout: A @ st (128x64), B @ st+16K (256x64)
template <int SWIGLU>
__device__ __forceinline__ void compute_stage(uint32_t st, int m0, int warpN, int lane, int warp,
                                              float acc[2][8][4]) {
    const uint32_t sA = st, sB = st + 16384;
#pragma unroll
    for (int kq = 0; kq < 4; kq++) {
        const int kk = (kq + warp) & 3;
        uint32_t a[2][4], b[4][4];
        ld_a16(sA, m0, lane, kk, a[0]);
        ld_a16(sA, m0 + 16, lane, kk, a[1]);
#pragma unroll
        for (int p = 0; p < 4; p++) {
            const int nb = SWIGLU ? ((p < 2) ? (warpN * 32 + p * 16) : (128 + warpN * 32 + (p - 2) * 16))
                                  : (warpN * 64 + p * 16);
            ld_b_pair(sB, nb, lane, kk, b[p]);
        }
#pragma unroll
        for (int mt = 0; mt < 2; mt++)
#pragma unroll
            for (int nt = 0; nt < 8; nt++)
                mma_f16(acc[mt][nt], a[mt], &b[nt >> 1][(nt & 1) * 2]);
    }
}

// ---------------- SwiGLU: Hf(fp16) = silu(A@W1) * (A@W3) ----------------
template <int MODE>
__global__ __launch_bounds__(NTHR, 1) void swiglu_tc() {
    constexpr int KT = DM;
    constexpr int NS = KT / 64;
    constexpr int NTOT = (MODE == 0) ? DFF : DFS;

    const int e = blockIdx.z;
    const __half *A, *B1, *B3;
    __half* Hf;
    int valid;
    if (MODE == 0) {
        valid = min(g_cnt[e], CAP);
        A = g_Xf + (size_t)e * CAP * DM;
        B1 = g_w1f + (size_t)e * DFF * DM;
        B3 = g_w3f + (size_t)e * DFF * DM;
        Hf = g_Hf + (size_t)e * CAP * DFF;
    } else {
        valid = T_TOK;
        A = g_hsf;
        B1 = g_ws1f; B3 = g_ws3f;
        Hf = g_Hsf;
    }
    const int row0 = blockIdx.y * 128;
    if (row0 >= valid) return;
    const int col0 = blockIdx.x * 128;

    extern __shared__ char smem[];
    const uint32_t sb = (smem_u32(smem) + 1023u) & ~1023u;

    const int tid = threadIdx.x, lane = tid & 31, warp = tid >> 5;
    const int warpM = warp & 3, warpN = warp >> 2;
    const int m0 = warpM * 32;

    float acc[2][8][4];
#pragma unroll
    for (int i = 0; i < 2; i++)
#pragma unroll
        for (int j = 0; j < 8; j++)
#pragma unroll
            for (int q = 0; q < 4; q++) acc[i][j][q] = 0.f;

#pragma unroll
    for (int s = 0; s < NSTAGE - 1; s++) {
        const uint32_t st = sb + s * STAGE_BYTES;
        const int k0 = s * 64;
        cpa_tile(A + (size_t)row0 * KT + k0, KT, st);
        cpa_tile_dual256(B1 + (size_t)col0 * KT + k0, B3 + (size_t)col0 * KT + k0, KT, st + 16384);
        CP_COMMIT();
    }

    for (int s = 0; s < NS; s++) {
        if (s >= NS - (NSTAGE - 1)) { CP_WAIT(0); } else { CP_WAIT(NSTAGE - 2); }
        __syncthreads();
        if (s + NSTAGE - 1 < NS) {
            const int sp = s + NSTAGE - 1;
            const uint32_t st = sb + (sp % NSTAGE) * STAGE_BYTES;
            const int k0 = sp * 64;
            cpa_tile(A + (size_t)row0 * KT + k0, KT, st);
            cpa_tile_dual256(B1 + (size_t)col0 * KT + k0, B3 + (size_t)col0 * KT + k0, KT, st + 16384);
            CP_COMMIT();
        }
        compute_stage<1>(sb + (s % NSTAGE) * STAGE_BYTES, m0, warpN, lane, warp, acc);
    }

#pragma unroll
    for (int mt = 0; mt < 2; mt++) {
        const int rbase = row0 + m0 + mt * 16 + (lane >> 2);
#pragma unroll
        for (int nt = 0; nt < 4; nt++) {
            const int col = col0 + warpN * 32 + nt * 8 + (lane & 3) * 2;
            float* c1 = acc[mt][nt];
            float* c3 = acc[mt][nt + 4];
            __half2 o0 = __floats2half2_rn(silu_f(c1[0]) * c3[0], silu_f(c1[1]) * c3[1]);
            __half2 o1 = __floats2half2_rn(silu_f(c1[2]) * c3[2], silu_f(c1[3]) * c3[3]);
            *reinterpret_cast<__half2*>(Hf + (size_t)rbase * NTOT + col) = o0;
            *reinterpret_cast<__half2*>(Hf + (size_t)(rbase + 8) * NTOT + col) = o1;
        }
    }
}

// ---------------- plain GEMM: O(fp32) = A @ W  (MODE 1 fuses routed-expert combine) ----------------
template <int MODE>
__global__ __launch_bounds__(NTHR, 1) void plain_tc(float* __restrict__ Oext) {
    constexpr int KT = (MODE == 0) ? DFF : DFS;
    constexpr int NS = KT / 64;

    const int e = blockIdx.z;
    const __half *A, *B;
    float* O;
    int valid;
    if (MODE == 0) {
        valid = min(g_cnt[e], CAP);
        A = g_Hf + (size_t)e * CAP * DFF;
        B = g_w2f + (size_t)e * DM * DFF;
        O = g_Y + (size_t)e * CAP * DM;
    } else {
        valid = T_TOK;
        A = g_Hsf;
        B = g_ws2f;
        O = Oext;
    }
    const int row0 = blockIdx.y * 128;
    if (row0 >= valid) return;
    const int col0 = blockIdx.x * 256;

    extern __shared__ char smem[];
    const uint32_t sb = (smem_u32(smem) + 1023u) & ~1023u;

    const int tid = threadIdx.x, lane = tid & 31, warp = tid >> 5;
    const int warpM = warp & 3, warpN = warp >> 2;
    const int m0 = warpM * 32;

    float acc[2][8][4];
#pragma unroll
    for (int i = 0; i < 2; i++)
#pragma unroll
        for (int j = 0; j < 8; j++)
#pragma unroll
            for (int q = 0; q < 4; q++) acc[i][j][q] = 0.f;

#pragma unroll
    for (int s = 0; s < NSTAGE - 1; s++) {
        if (s >= NS) break;
        const uint32_t st = sb + s * STAGE_BYTES;
        const int k0 = s * 64;
        cpa_tile(A + (size_t)row0 * KT + k0, KT, st);
        cpa_tile256(B + (size_t)col0 * KT + k0, KT, st + 16384);
        CP_COMMIT();
    }

    for (int s = 0; s < NS; s++) {
        if (s >= NS - (NSTAGE - 1)) { CP_WAIT(0); } else { CP_WAIT(NSTAGE - 2); }
        __syncthreads();
        if (s + NSTAGE - 1 < NS) {
            const int sp = s + NSTAGE - 1;
            const uint32_t st = sb + (sp % NSTAGE) * STAGE_BYTES;
            const int k0 = sp * 64;
            cpa_tile(A + (size_t)row0 * KT + k0, KT, st);
            cpa_tile256(B + (size_t)col0 * KT + k0, KT, st + 16384);
            CP_COMMIT();
        }
        compute_stage<0>(sb + (s % NSTAGE) * STAGE_BYTES, m0, warpN, lane, warp, acc);
    }

#pragma unroll
    for (int mt = 0; mt < 2; mt++) {
        const int r0 = row0 + m0 + mt * 16 + (lane >> 2);
        const int r1 = r0 + 8;
        int s0a = -1, s1a = -1, s0b = -1, s1b = -1;
        float w0a = 0.f, w1a = 0.f, w0b = 0.f, w1b = 0.f;
        if (MODE == 1) {
            s0a = g_slot[2 * r0];     s1a = g_slot[2 * r0 + 1];
            w0a = g_wt[2 * r0];       w1a = g_wt[2 * r0 + 1];
            s0b = g_slot[2 * r1];     s1b = g_slot[2 * r1 + 1];
            w0b = g_wt[2 * r1];       w1b = g_wt[2 * r1 + 1];
        }
#pragma unroll
        for (int nt = 0; nt < 8; nt++) {
            const int col = col0 + warpN * 64 + nt * 8 + (lane & 3) * 2;
            float* c = acc[mt][nt];
            float2 v0 = make_float2(c[0], c[1]);
            float2 v1 = make_float2(c[2], c[3]);
            if (MODE == 1) {
                if (s0a >= 0) {
                    float2 y = *reinterpret_cast<const float2*>(&g_Y[(size_t)s0a * DM + col]);
                    v0.x += w0a * y.x; v0.y += w0a * y.y;
                }
                if (s1a >= 0) {
                    float2 y = *reinterpret_cast<const float2*>(&g_Y[(size_t)s1a * DM + col]);
                    v0.x += w1a * y.x; v0.y += w1a * y.y;
                }
                if (s0b >= 0) {
                    float2 y = *reinterpret_cast<const float2*>(&g_Y[(size_t)s0b * DM + col]);
                    v1.x += w0b * y.x; v1.y += w0b * y.y;
                }
                if (s1b >= 0) {
                    float2 y = *reinterpret_cast<const float2*>(&g_Y[(size_t)s1b * DM + col]);
                    v1.x += w1b * y.x; v1.y += w1b * y.y;
                }
            }
            *reinterpret_cast<float2*>(O + (size_t)r0 * DM + col) = v0;
            *reinterpret_cast<float2*>(O + (size_t)r1 * DM + col) = v1;
        }
    }
}

// ---------------- launch (two-chain fork/join; R12 schedule) ----------------
extern "C" void kernel_launch(void* const* d_in, const int* in_sizes, int n_in,
                              void* d_out, int out_size) {
    const float* hs  = (const float*)d_in[0];
    const float* Wg  = (const float*)d_in[1];
    const float* w1  = (const float*)d_in[2];
    const float* w3  = (const float*)d_in[3];
    const float* w2  = (const float*)d_in[4];
    const float* ws1 = (const float*)d_in[5];
    const float* ws3 = (const float*)d_in[6];
    const float* ws2 = (const float*)d_in[7];
    float* out = (float*)d_out;

    static cudaStream_t side = nullptr;
    static cudaEvent_t ev0 = nullptr, ev_r = nullptr, ev_up = nullptr, ev_dn = nullptr, evA = nullptr;
    if (side == nullptr) {
        cudaStreamCreateWithFlags(&side, cudaStreamNonBlocking);
        cudaEventCreateWithFlags(&ev0,  cudaEventDisableTiming);
        cudaEventCreateWithFlags(&ev_r, cudaEventDisableTiming);
        cudaEventCreateWithFlags(&ev_up, cudaEventDisableTiming);
        cudaEventCreateWithFlags(&ev_dn, cudaEventDisableTiming);
        cudaEventCreateWithFlags(&evA,  cudaEventDisableTiming);
        cudaFuncSetAttribute(swiglu_tc<0>, cudaFuncAttributeMaxDynamicSharedMemorySize, SMEM_BYTES);
        cudaFuncSetAttribute(swiglu_tc<1>, cudaFuncAttributeMaxDynamicSharedMemorySize, SMEM_BYTES);
        cudaFuncSetAttribute(plain_tc<0>,  cudaFuncAttributeMaxDynamicSharedMemorySize, SMEM_BYTES);
        cudaFuncSetAttribute(plain_tc<1>,  cudaFuncAttributeMaxDynamicSharedMemorySize, SMEM_BYTES);
    }

    // fork: side = router; main = weight converts (up first so GEMMs start early)
    cudaEventRecord(ev0, 0);
    cudaStreamWaitEvent(side, ev0, 0);
    zero_cnt_kernel<<<1, 32, 0, side>>>();
    router_kernel<<<T_TOK / 8, 256, 0, side>>>(hs, Wg);
    cudaEventRecord(ev_r, side);

    wsplit_up<<<18432, dim3(32, 8)>>>(w1, w3, ws1, ws3);
    cudaEventRecord(ev_up, 0);
    wsplit_down<<<9216, dim3(32, 8)>>>(w2, ws2);
    cudaEventRecord(ev_dn, 0);

    // side chain: expert swiglu -> expert down-proj
    cudaStreamWaitEvent(side, ev_up, 0);
    swiglu_tc<0><<<dim3(DFF / 128, CAP / 128, NE), NTHR, SMEM_BYTES, side>>>();
    cudaStreamWaitEvent(side, ev_dn, 0);
    plain_tc<0><<<dim3(DM / 256, CAP / 128, NE), NTHR, SMEM_BYTES, side>>>(nullptr);
    cudaEventRecord(evA, side);

    // main chain: shared swiglu (needs router gather of hs + up weights)
    cudaStreamWaitEvent(0, ev_r, 0);
    swiglu_tc<1><<<dim3(DFS / 128, T_TOK / 128, 1), NTHR, SMEM_BYTES>>>();

    // join: shared down-proj writes d_out with fused routed combine (needs g_Y)
    cudaStreamWaitEvent(0, evA, 0);
    plain_tc<1><<<dim3(DM / 256, T_TOK / 128, 1), NTHR, SMEM_BYTES>>>(out);
}

// round 17
// speedup vs baseline: 1.0367x; 1.0367x over previous
#include <cuda_runtime.h>
#include <cuda_fp16.h>
#include <cstdint>
#include <math.h>

#define T_TOK 4096
#define DM    1024
#define NE    16
#define CAP   1024
#define DFF   512
#define DFS   1024
#define NTHR  512

// ---------------- scratch ----------------
__device__ int   g_cnt[NE];
__device__ int   g_slot[T_TOK * 2];
__device__ float g_wt[T_TOK * 2];
__device__ float g_Y [(size_t)NE * CAP * DM];

// activations: fp16
__device__ __half g_Xf [(size_t)NE * CAP * DM];
__device__ __half g_Hf [(size_t)NE * CAP * DFF];
__device__ __half g_hsf[(size_t)T_TOK * DM];
__device__ __half g_Hsf[(size_t)T_TOK * DFS];

// weights: fp16, transposed to [N, K]
__device__ __half g_w1f[(size_t)NE * DFF * DM];
__device__ __half g_w3f[(size_t)NE * DFF * DM];
__device__ __half g_w2f[(size_t)NE * DM * DFF];
__device__ __half g_ws1f[(size_t)DFS * DM];
__device__ __half g_ws3f[(size_t)DFS * DM];
__device__ __half g_ws2f[(size_t)DM * DFS];

// ---------------- helpers ----------------
__device__ __forceinline__ uint32_t smem_u32(const void* p) {
    uint32_t r;
    asm("{ .reg .u64 t; cvta.to.shared.u64 t, %1; cvt.u32.u64 %0, t; }" : "=r"(r) : "l"(p));
    return r;
}

#define LDSM_X4(r0, r1, r2, r3, addr) \
    asm volatile("ldmatrix.sync.aligned.m8n8.x4.shared.b16 {%0,%1,%2,%3}, [%4];" \
                 : "=r"(r0), "=r"(r1), "=r"(r2), "=r"(r3) : "r"(addr))

__device__ __forceinline__ void mma_f16(float* c, const uint32_t* a, const uint32_t* b) {
    asm volatile("mma.sync.aligned.m16n8k16.row.col.f32.f16.f16.f32 "
                 "{%0,%1,%2,%3}, {%4,%5,%6,%7}, {%8,%9}, {%0,%1,%2,%3};"
                 : "+f"(c[0]), "+f"(c[1]), "+f"(c[2]), "+f"(c[3])
                 : "r"(a[0]), "r"(a[1]), "r"(a[2]), "r"(a[3]), "r"(b[0]), "r"(b[1]));
}

#define CP_ASYNC16(dst, src) \
    asm volatile("{ .reg .u64 g; cvta.to.global.u64 g, %1; " \
                 "cp.async.cg.shared.global [%0], [g], 16; }" \
                 :: "r"(dst), "l"(src) : "memory")
#define CP_COMMIT() asm volatile("cp.async.commit_group;" ::: "memory")
#define CP_WAIT(n)  asm volatile("cp.async.wait_group %0;" :: "n"(n) : "memory")

__device__ __forceinline__ uint32_t swz(uint32_t base, int r, int byteoff) {
    return base + (uint32_t)(r * 128) + (uint32_t)(((((byteoff >> 4) ^ (r & 7)) << 4)) | (byteoff & 15));
}

// A tile: 128 rows x 64 k (16KB)
__device__ __forceinline__ void cpa_tile(const __half* __restrict__ src, int ldk, uint32_t dst) {
    const int tid = threadIdx.x;
#pragma unroll
    for (int k = 0; k < 2; k++) {
        const int i = tid + k * NTHR;
        const int r = i >> 3, c = i & 7;
        const uint32_t off = (uint32_t)(r * 128 + ((c ^ (r & 7)) << 4));
        CP_ASYNC16(dst + off, src + (size_t)r * ldk + c * 8);
    }
}

// B tile: 256 rows x 64 k (32KB), single source
__device__ __forceinline__ void cpa_tile256(const __half* __restrict__ src, int ldk, uint32_t dst) {
    const int tid = threadIdx.x;
#pragma unroll
    for (int k = 0; k < 4; k++) {
        const int i = tid + k * NTHR;
        const int r = i >> 3, c = i & 7;
        const uint32_t off = (uint32_t)(r * 128 + ((c ^ (r & 7)) << 4));
        CP_ASYNC16(dst + off, src + (size_t)r * ldk + c * 8);
    }
}

// B tile: rows 0..127 from b1, 128..255 from b3 (SwiGLU)
__device__ __forceinline__ void cpa_tile_dual256(const __half* __restrict__ b1,
                                                 const __half* __restrict__ b3,
                                                 int ldk, uint32_t dst) {
    const int tid = threadIdx.x;
#pragma unroll
    for (int k = 0; k < 4; k++) {
        const int i = tid + k * NTHR;
        const int r = i >> 3, c = i & 7;
        const __half* s = (r < 128) ? b1 + (size_t)r * ldk + c * 8
                                    : b3 + (size_t)(r - 128) * ldk + c * 8;
        const uint32_t off = (uint32_t)(r * 128 + ((c ^ (r & 7)) << 4));
        CP_ASYNC16(dst + off, s);
    }
}

#define NSTAGE 4
#define STAGE_BYTES 49152           // A(16K) + B(32K)
#define SMEM_BYTES (NSTAGE * STAGE_BYTES + 1024)

// ---------------- weight transpose + fp16 convert prepass ----------------
// tile 64(k) x 32(n); 256 threads; loads 128B-coalesced, stores 128B segments (uint4/thread)
__device__ __forceinline__ void wsplit_tile(const float* __restrict__ W,
                                            __half* __restrict__ of,
                                            int K, int N, int e, int rem) {
    const int ntiles_n = N >> 5;
    const int kb = (rem / ntiles_n) * 64, nb = (rem % ntiles_n) * 32;
    const size_t eoff = (size_t)e * K * N;
    W += eoff; of += eoff;

    __shared__ float t[64][33];
    const int u = threadIdx.x;   // 0..255
#pragma unroll
    for (int i = 0; i < 2; i++) {
        const int idx = u + 256 * i;          // 0..511
        const int kr = idx >> 3;              // k row 0..63
        const int cg = (idx & 7) * 4;         // n col group
        float4 v = *reinterpret_cast<const float4*>(&W[(size_t)(kb + kr) * N + nb + cg]);
        t[kr][cg] = v.x; t[kr][cg + 1] = v.y; t[kr][cg + 2] = v.z; t[kr][cg + 3] = v.w;
    }
    __syncthreads();

    const int n  = u >> 3;                    // 0..31
    const int kg = (u & 7) * 8;               // 0,8,...,56
    __half2 h[4];
#pragma unroll
    for (int j = 0; j < 4; j++)
        h[j] = __floats2half2_rn(t[kg + 2 * j][n], t[kg + 2 * j + 1][n]);
    uint4 o;
    __builtin_memcpy(&o.x, &h[0], 4);
    __builtin_memcpy(&o.y, &h[1], 4);
    __builtin_memcpy(&o.z, &h[2], 4);
    __builtin_memcpy(&o.w, &h[3], 4);
    *reinterpret_cast<uint4*>(&of[(size_t)(nb + n) * K + kb + kg]) = o;
}

// up: w1 (4096) | w3 (4096) | ws1 (512) | ws3 (512) -> 9216 blocks (tiles of 64k x 32n)
__global__ void wsplit_up(const float* __restrict__ w1, const float* __restrict__ w3,
                          const float* __restrict__ ws1, const float* __restrict__ ws3) {
    int id = blockIdx.x;
    if (id < 4096)      { wsplit_tile(w1,  g_w1f,  DM, DFF, id >> 8, id & 255); }
    else if (id < 8192) { id -= 4096; wsplit_tile(w3,  g_w3f,  DM, DFF, id >> 8, id & 255); }
    else if (id < 8704) { id -= 8192; wsplit_tile(ws1, g_ws1f, DM, DFS, 0, id); }
    else                { id -= 8704; wsplit_tile(ws3, g_ws3f, DM, DFS, 0, id); }
}

// down: w2 (4096) | ws2 (512) -> 4608 blocks
__global__ void wsplit_down(const float* __restrict__ w2, const float* __restrict__ ws2) {
    int id = blockIdx.x;
    if (id < 4096) { wsplit_tile(w2, g_w2f, DFF, DM, id >> 8, id & 255); }
    else           { id -= 4096; wsplit_tile(ws2, g_ws2f, DFS, DM, 0, id); }
}

// ---------------- counters reset ----------------
__global__ void zero_cnt_kernel() {
    if (threadIdx.x < NE) g_cnt[threadIdx.x] = 0;
}

// ---------------- router ----------------
__global__ void router_kernel(const float* __restrict__ hs, const float* __restrict__ Wg) {
    __shared__ float sW[NE * 513];
    const int tid = threadIdx.x, lane = tid & 31, wid = tid >> 5;
    const int t = blockIdx.x * 8 + wid;

    float hreg[32];
#pragma unroll
    for (int j = 0; j < 32; j++) hreg[j] = hs[(size_t)t * DM + j * 32 + lane];

    __half hh[32];
#pragma unroll
    for (int j = 0; j < 32; j++) hh[j] = __float2half_rn(hreg[j]);
#pragma unroll
    for (int j = 0; j < 32; j++)
        g_hsf[(size_t)t * DM + j * 32 + lane] = hh[j];

    float plog[NE];
#pragma unroll
    for (int e = 0; e < NE; e++) plog[e] = 0.f;

    for (int c = 0; c < 2; c++) {
        __syncthreads();
        for (int i = tid; i < 512 * NE; i += 256) {
            int d = i >> 4, e = i & 15;
            sW[e * 513 + d] = Wg[(size_t)c * 8192 + i];
        }
        __syncthreads();
#pragma unroll
        for (int e = 0; e < NE; e++) {
            float s = 0.f;
#pragma unroll
            for (int j = 0; j < 16; j++)
                s += hreg[c * 16 + j] * sW[e * 513 + j * 32 + lane];
            plog[e] += s;
        }
    }
#pragma unroll
    for (int e = 0; e < NE; e++) {
        float v = plog[e];
#pragma unroll
        for (int o = 16; o > 0; o >>= 1) v += __shfl_xor_sync(0xffffffffu, v, o);
        plog[e] = v;
    }
    float mx = plog[0];
#pragma unroll
    for (int e = 1; e < NE; e++) mx = fmaxf(mx, plog[e]);
#pragma unroll
    for (int e = 0; e < NE; e++) plog[e] = expf(plog[e] - mx);
    int e0 = 0; float p0 = plog[0];
#pragma unroll
    for (int e = 1; e < NE; e++) if (plog[e] > p0) { p0 = plog[e]; e0 = e; }
    int e1 = 0; float p1 = -1.f;
#pragma unroll
    for (int e = 0; e < NE; e++) if (e != e0 && plog[e] > p1) { p1 = plog[e]; e1 = e; }
    const float rnorm = 1.f / (p0 + p1);
    const float w0 = p0 * rnorm, w1 = p1 * rnorm;

    int s0 = 0, s1 = 0;
    if (lane == 0) {
        int pos = atomicAdd(&g_cnt[e0], 1);
        s0 = (pos < CAP) ? e0 * CAP + pos : -1;
        pos = atomicAdd(&g_cnt[e1], 1);
        s1 = (pos < CAP) ? e1 * CAP + pos : -1;
        g_slot[t * 2] = s0; g_slot[t * 2 + 1] = s1;
        g_wt[t * 2] = w0;   g_wt[t * 2 + 1] = w1;
    }
    s0 = __shfl_sync(0xffffffffu, s0, 0);
    s1 = __shfl_sync(0xffffffffu, s1, 0);
    if (s0 >= 0) {
#pragma unroll
        for (int j = 0; j < 32; j++)
            g_Xf[(size_t)s0 * DM + j * 32 + lane] = hh[j];
    }
    if (s1 >= 0) {
#pragma unroll
        for (int j = 0; j < 32; j++)
            g_Xf[(size_t)s1 * DM + j * 32 + lane] = hh[j];
    }
}

// ======================= fp16 1-term HMMA GEMM kernels (R12 config) =======================
// 16 warps as 4(M) x 4(N); warp tile 32 rows x 64 cols; per warp per kk:
// 2 A-LDSM + 4 B-LDSM, 16 MMA.

__device__ __forceinline__ void ld_a16(uint32_t sA, int r0, int lane, int kk, uint32_t a[4]) {
    const int r = r0 + (lane & 15);
    const int byte = kk * 32 + ((lane >> 4) << 4);
    LDSM_X4(a[0], a[1], a[2], a[3], swz(sA, r, byte));
}

__device__ __forceinline__ void ld_b_pair(uint32_t sB, int nb, int lane, int kk, uint32_t b[4]) {
    const int r = nb + ((lane >> 4) << 3) + (lane & 7);
    const int byte = kk * 32 + (((lane >> 3) & 1) << 4);
    LDSM_X4(b[0], b[1], b[2], b[3], swz(sB, r, byte));
}

__device__ __forceinline__ float silu_f(float x) {
    return x / (1.f + __expf(-x));
}

// stage layout: A @ st (128x64), B @ st+16K (256x64)
template <int SWIGLU>
__device__ __forceinline__ void compute_stage(uint32_t st, int m0, int warpN, int lane, int warp,
                                              float acc[2][8][4]) {
    const uint32_t sA = st, sB = st + 16384;
#pragma unroll
    for (int kq = 0; kq < 4; kq++) {
        const int kk = (kq + warp) & 3;
        uint32_t a[2][4], b[4][4];
        ld_a16(sA, m0, lane, kk, a[0]);
        ld_a16(sA, m0 + 16, lane, kk, a[1]);
#pragma unroll
        for (int p = 0; p < 4; p++) {
            const int nb = SWIGLU ? ((p < 2) ? (warpN * 32 + p * 16) : (128 + warpN * 32 + (p - 2) * 16))
                                  : (warpN * 64 + p * 16);
            ld_b_pair(sB, nb, lane, kk, b[p]);
        }
#pragma unroll
        for (int mt = 0; mt < 2; mt++)
#pragma unroll
            for (int nt = 0; nt < 8; nt++)
                mma_f16(acc[mt][nt], a[mt], &b[nt >> 1][(nt & 1) * 2]);
    }
}

// ---------------- SwiGLU: Hf(fp16) = silu(A@W1) * (A@W3) ----------------
template <int MODE>
__global__ __launch_bounds__(NTHR, 1) void swiglu_tc() {
    constexpr int KT = DM;
    constexpr int NS = KT / 64;
    constexpr int NTOT = (MODE == 0) ? DFF : DFS;

    const int e = blockIdx.z;
    const __half *A, *B1, *B3;
    __half* Hf;
    int valid;
    if (MODE == 0) {
        valid = min(g_cnt[e], CAP);
        A = g_Xf + (size_t)e * CAP * DM;
        B1 = g_w1f + (size_t)e * DFF * DM;
        B3 = g_w3f + (size_t)e * DFF * DM;
        Hf = g_Hf + (size_t)e * CAP * DFF;
    } else {
        valid = T_TOK;
        A = g_hsf;
        B1 = g_ws1f; B3 = g_ws3f;
        Hf = g_Hsf;
    }
    const int row0 = blockIdx.y * 128;
    if (row0 >= valid) return;
    const int col0 = blockIdx.x * 128;

    extern __shared__ char smem[];
    const uint32_t sb = (smem_u32(smem) + 1023u) & ~1023u;

    const int tid = threadIdx.x, lane = tid & 31, warp = tid >> 5;
    const int warpM = warp & 3, warpN = warp >> 2;
    const int m0 = warpM * 32;

    float acc[2][8][4];
#pragma unroll
    for (int i = 0; i < 2; i++)
#pragma unroll
        for (int j = 0; j < 8; j++)
#pragma unroll
            for (int q = 0; q < 4; q++) acc[i][j][q] = 0.f;

#pragma unroll
    for (int s = 0; s < NSTAGE - 1; s++) {
        const uint32_t st = sb + s * STAGE_BYTES;
        const int k0 = s * 64;
        cpa_tile(A + (size_t)row0 * KT + k0, KT, st);
        cpa_tile_dual256(B1 + (size_t)col0 * KT + k0, B3 + (size_t)col0 * KT + k0, KT, st + 16384);
        CP_COMMIT();
    }

    for (int s = 0; s < NS; s++) {
        if (s >= NS - (NSTAGE - 1)) { CP_WAIT(0); } else { CP_WAIT(NSTAGE - 2); }
        __syncthreads();
        if (s + NSTAGE - 1 < NS) {
            const int sp = s + NSTAGE - 1;
            const uint32_t st = sb + (sp % NSTAGE) * STAGE_BYTES;
            const int k0 = sp * 64;
            cpa_tile(A + (size_t)row0 * KT + k0, KT, st);
            cpa_tile_dual256(B1 + (size_t)col0 * KT + k0, B3 + (size_t)col0 * KT + k0, KT, st + 16384);
            CP_COMMIT();
        }
        compute_stage<1>(sb + (s % NSTAGE) * STAGE_BYTES, m0, warpN, lane, warp, acc);
    }

#pragma unroll
    for (int mt = 0; mt < 2; mt++) {
        const int rbase = row0 + m0 + mt * 16 + (lane >> 2);
#pragma unroll
        for (int nt = 0; nt < 4; nt++) {
            const int col = col0 + warpN * 32 + nt * 8 + (lane & 3) * 2;
            float* c1 = acc[mt][nt];
            float* c3 = acc[mt][nt + 4];
            __half2 o0 = __floats2half2_rn(silu_f(c1[0]) * c3[0], silu_f(c1[1]) * c3[1]);
            __half2 o1 = __floats2half2_rn(silu_f(c1[2]) * c3[2], silu_f(c1[3]) * c3[3]);
            *reinterpret_cast<__half2*>(Hf + (size_t)rbase * NTOT + col) = o0;
            *reinterpret_cast<__half2*>(Hf + (size_t)(rbase + 8) * NTOT + col) = o1;
        }
    }
}

// ---------------- plain GEMM: O(fp32) = A @ W  (MODE 1 fuses routed-expert combine) ----------------
template <int MODE>
__global__ __launch_bounds__(NTHR, 1) void plain_tc(float* __restrict__ Oext) {
    constexpr int KT = (MODE == 0) ? DFF : DFS;
    constexpr int NS = KT / 64;

    const int e = blockIdx.z;
    const __half *A, *B;
    float* O;
    int valid;
    if (MODE == 0) {
        valid = min(g_cnt[e], CAP);
        A = g_Hf + (size_t)e * CAP * DFF;
        B = g_w2f + (size_t)e * DM * DFF;
        O = g_Y + (size_t)e * CAP * DM;
    } else {
        valid = T_TOK;
        A = g_Hsf;
        B = g_ws2f;
        O = Oext;
    }
    const int row0 = blockIdx.y * 128;
    if (row0 >= valid) return;
    const int col0 = blockIdx.x * 256;

    extern __shared__ char smem[];
    const uint32_t sb = (smem_u32(smem) + 1023u) & ~1023u;

    const int tid = threadIdx.x, lane = tid & 31, warp = tid >> 5;
    const int warpM = warp & 3, warpN = warp >> 2;
    const int m0 = warpM * 32;

    float acc[2][8][4];
#pragma unroll
    for (int i = 0; i < 2; i++)
#pragma unroll
        for (int j = 0; j < 8; j++)
#pragma unroll
            for (int q = 0; q < 4; q++) acc[i][j][q] = 0.f;

#pragma unroll
    for (int s = 0; s < NSTAGE - 1; s++) {
        if (s >= NS) break;
        const uint32_t st = sb + s * STAGE_BYTES;
        const int k0 = s * 64;
        cpa_tile(A + (size_t)row0 * KT + k0, KT, st);
        cpa_tile256(B + (size_t)col0 * KT + k0, KT, st + 16384);
        CP_COMMIT();
    }

    for (int s = 0; s < NS; s++) {
        if (s >= NS - (NSTAGE - 1)) { CP_WAIT(0); } else { CP_WAIT(NSTAGE - 2); }
        __syncthreads();
        if (s + NSTAGE - 1 < NS) {
            const int sp = s + NSTAGE - 1;
            const uint32_t st = sb + (sp % NSTAGE) * STAGE_BYTES;
            const int k0 = sp * 64;
            cpa_tile(A + (size_t)row0 * KT + k0, KT, st);
            cpa_tile256(B + (size_t)col0 * KT + k0, KT, st + 16384);
            CP_COMMIT();
        }
        compute_stage<0>(sb + (s % NSTAGE) * STAGE_BYTES, m0, warpN, lane, warp, acc);
    }

#pragma unroll
    for (int mt = 0; mt < 2; mt++) {
        const int r0 = row0 + m0 + mt * 16 + (lane >> 2);
        const int r1 = r0 + 8;
        int s0a = -1, s1a = -1, s0b = -1, s1b = -1;
        float w0a = 0.f, w1a = 0.f, w0b = 0.f, w1b = 0.f;
        if (MODE == 1) {
            s0a = g_slot[2 * r0];     s1a = g_slot[2 * r0 + 1];
            w0a = g_wt[2 * r0];       w1a = g_wt[2 * r0 + 1];
            s0b = g_slot[2 * r1];     s1b = g_slot[2 * r1 + 1];
            w0b = g_wt[2 * r1];       w1b = g_wt[2 * r1 + 1];
        }
#pragma unroll
        for (int nt = 0; nt < 8; nt++) {
            const int col = col0 + warpN * 64 + nt * 8 + (lane & 3) * 2;
            float* c = acc[mt][nt];
            float2 v0 = make_float2(c[0], c[1]);
            float2 v1 = make_float2(c[2], c[3]);
            if (MODE == 1) {
                if (s0a >= 0) {
                    float2 y = *reinterpret_cast<const float2*>(&g_Y[(size_t)s0a * DM + col]);
                    v0.x += w0a * y.x; v0.y += w0a * y.y;
                }
                if (s1a >= 0) {
                    float2 y = *reinterpret_cast<const float2*>(&g_Y[(size_t)s1a * DM + col]);
                    v0.x += w1a * y.x; v0.y += w1a * y.y;
                }
                if (s0b >= 0) {
                    float2 y = *reinterpret_cast<const float2*>(&g_Y[(size_t)s0b * DM + col]);
                    v1.x += w0b * y.x; v1.y += w0b * y.y;
                }
                if (s1b >= 0) {
                    float2 y = *reinterpret_cast<const float2*>(&g_Y[(size_t)s1b * DM + col]);
                    v1.x += w1b * y.x; v1.y += w1b * y.y;
                }
            }
            *reinterpret_cast<float2*>(O + (size_t)r0 * DM + col) = v0;
            *reinterpret_cast<float2*>(O + (size_t)r1 * DM + col) = v1;
        }
    }
}

// ---------------- launch (two-chain fork/join; R12 schedule) ----------------
extern "C" void kernel_launch(void* const* d_in, const int* in_sizes, int n_in,
                              void* d_out, int out_size) {
    const float* hs  = (const float*)d_in[0];
    const float* Wg  = (const float*)d_in[1];
    const float* w1  = (const float*)d_in[2];
    const float* w3  = (const float*)d_in[3];
    const float* w2  = (const float*)d_in[4];
    const float* ws1 = (const float*)d_in[5];
    const float* ws3 = (const float*)d_in[6];
    const float* ws2 = (const float*)d_in[7];
    float* out = (float*)d_out;

    static cudaStream_t side = nullptr;
    static cudaEvent_t ev0 = nullptr, ev_r = nullptr, ev_up = nullptr, ev_dn = nullptr, evA = nullptr;
    if (side == nullptr) {
        cudaStreamCreateWithFlags(&side, cudaStreamNonBlocking);
        cudaEventCreateWithFlags(&ev0,  cudaEventDisableTiming);
        cudaEventCreateWithFlags(&ev_r, cudaEventDisableTiming);
        cudaEventCreateWithFlags(&ev_up, cudaEventDisableTiming);
        cudaEventCreateWithFlags(&ev_dn, cudaEventDisableTiming);
        cudaEventCreateWithFlags(&evA,  cudaEventDisableTiming);
        cudaFuncSetAttribute(swiglu_tc<0>, cudaFuncAttributeMaxDynamicSharedMemorySize, SMEM_BYTES);
        cudaFuncSetAttribute(swiglu_tc<1>, cudaFuncAttributeMaxDynamicSharedMemorySize, SMEM_BYTES);
        cudaFuncSetAttribute(plain_tc<0>,  cudaFuncAttributeMaxDynamicSharedMemorySize, SMEM_BYTES);
        cudaFuncSetAttribute(plain_tc<1>,  cudaFuncAttributeMaxDynamicSharedMemorySize, SMEM_BYTES);
    }

    // fork: side = router; main = weight converts (up first so GEMMs start early)
    cudaEventRecord(ev0, 0);
    cudaStreamWaitEvent(side, ev0, 0);
    zero_cnt_kernel<<<1, 32, 0, side>>>();
    router_kernel<<<T_TOK / 8, 256, 0, side>>>(hs, Wg);
    cudaEventRecord(ev_r, side);

    wsplit_up<<<9216, 256>>>(w1, w3, ws1, ws3);
    cudaEventRecord(ev_up, 0);
    wsplit_down<<<4608, 256>>>(w2, ws2);
    cudaEventRecord(ev_dn, 0);

    // side chain: expert swiglu -> expert down-proj
    cudaStreamWaitEvent(side, ev_up, 0);
    swiglu_tc<0><<<dim3(DFF / 128, CAP / 128, NE), NTHR, SMEM_BYTES, side>>>();
    cudaStreamWaitEvent(side, ev_dn, 0);
    plain_tc<0><<<dim3(DM / 256, CAP / 128, NE), NTHR, SMEM_BYTES, side>>>(nullptr);
    cudaEventRecord(evA, side);

    // main chain: shared swiglu (needs router gather of hs + up weights)
    cudaStreamWaitEvent(0, ev_r, 0);
    swiglu_tc<1><<<dim3(DFS / 128, T_TOK / 128, 1), NTHR, SMEM_BYTES>>>();

    // join: shared down-proj writes d_out with fused routed combine (needs g_Y)
    cudaStreamWaitEvent(0, evA, 0);
    plain_tc<1><<<dim3(DM / 256, T_TOK / 128, 1), NTHR, SMEM_BYTES>>>(out);
}